// round 10
// baseline (speedup 1.0000x reference)
#include <cuda_runtime.h>

#define N_FFT    1024
#define HOP      512
#define CUTOFF   513
#define BATCH    16
#define T_LEN    2097152
#define N_FRAMES 4095
#define TILE     8       // 8 frames = 4 pair-packed complex FFTs per block
#define THREADS  256
#define MP       10      // mag row pad (even -> float2 stores; 5k+v banking <=2-way)

__device__ __forceinline__ float2 cmul(float2 a, float2 b) {
    return make_float2(a.x * b.x - a.y * b.y, a.x * b.y + a.y * b.x);
}

// In-register radix-4 butterfly (DIT, W4 = -i), outputs in natural order.
__device__ __forceinline__ void dft4(float2& a, float2& b, float2& c, float2& d) {
    float2 apc  = make_float2(a.x + c.x, a.y + c.y);
    float2 amc  = make_float2(a.x - c.x, a.y - c.y);
    float2 bpd  = make_float2(b.x + d.x, b.y + d.y);
    float2 jbmd = make_float2(-(b.y - d.y), b.x - d.x);   // i*(b-d)
    a = make_float2(apc.x + bpd.x, apc.y + bpd.y);
    b = make_float2(amc.x - jbmd.x, amc.y - jbmd.y);
    c = make_float2(apc.x - bpd.x, apc.y - bpd.y);
    d = make_float2(amc.x + jbmd.x, amc.y + jbmd.y);
}

// 16-point DFT fully in registers. Input z[n]; output y[k] at slot 4*(k&3)+(k>>2).
__device__ __forceinline__ void dft16(float2 z[16]) {
    #pragma unroll
    for (int b = 0; b < 4; b++) dft4(z[b], z[4 + b], z[8 + b], z[12 + b]);
    const float C1 = 0.9238795325112867f, S1 = 0.3826834323650898f, R2 = 0.7071067811865476f;
    const float2 W1 = make_float2( C1, -S1);
    const float2 W2 = make_float2( R2, -R2);
    const float2 W3 = make_float2( S1, -C1);
    const float2 W6 = make_float2(-R2, -R2);
    const float2 W9 = make_float2(-C1,  S1);
    z[5]  = cmul(z[5],  W1);
    z[9]  = cmul(z[9],  W2);
    z[13] = cmul(z[13], W3);
    z[6]  = cmul(z[6],  W2);
    z[10] = make_float2(z[10].y, -z[10].x);   // * W16^4 = -i
    z[14] = cmul(z[14], W6);
    z[7]  = cmul(z[7],  W3);
    z[11] = cmul(z[11], W6);
    z[15] = cmul(z[15], W9);
    #pragma unroll
    for (int c = 0; c < 4; c++) dft4(z[4*c], z[4*c + 1], z[4*c + 2], z[4*c + 3]);
}

// lo[i] = t^i, hi[i] = t^(4i): acc(k) = lo[k&3]*hi[k>>2], short dep chains.
__device__ __forceinline__ void make_pows(float2 t, float2 lo[4], float2 hi[4]) {
    lo[0] = make_float2(1.f, 0.f);
    lo[1] = t;
    lo[2] = cmul(t, t);
    lo[3] = cmul(lo[2], t);
    hi[0] = make_float2(1.f, 0.f);
    hi[1] = cmul(lo[2], lo[2]);
    hi[2] = cmul(hi[1], hi[1]);
    hi[3] = cmul(hi[2], hi[1]);
}

// Read quad (K,J): 4 contiguous complex m2-values -> 2x LDS.128 (<=2-way).
__device__ __forceinline__ void load_quad(const float2* __restrict__ fb, int K, int J, float2 q[4]) {
    const float4* p = (const float4*)(fb + 64 * K + 4 * (J ^ (K & 3)));
    float4 h0 = p[0], h1 = p[1];
    q[0] = make_float2(h0.x, h0.y);
    q[1] = make_float2(h0.z, h0.w);
    q[2] = make_float2(h1.x, h1.y);
    q[3] = make_float2(h1.z, h1.w);
}

// P,Q conjugate pair of the pair-packed FFT -> two frame magnitudes at bin k.
// |0.5*z| = 0.5*|z|; sqrt via rsqrt (MUFU.RSQ), +1e-30 guards s==0.
__device__ __forceinline__ void pair_mags(float* mag, int k, int v2, float2 P, float2 Q) {
    float Ar = P.x + Q.x, Ai = P.y - Q.y;
    float Br = P.y + Q.y, Bi = Q.x - P.x;
    float sa = fmaf(Ar, Ar, Ai * Ai) + 1e-30f;
    float sb = fmaf(Br, Br, Bi * Bi) + 1e-30f;
    float ma = 0.5f * (sa * __frsqrt_rn(sa));
    float mb = 0.5f * (sb * __frsqrt_rn(sb));
    *(float2*)(mag + k * MP + v2) = make_float2(ma, mb);   // even addr -> STS.64
}

// One orbit: quad A=(k1,j1) and its conjugate quad B. Emits 4 bins.
__device__ __forceinline__ void orbit_mags(const float2* __restrict__ fb, float* mag, int v2,
                                           int k1, int j1, int k1B, int j1B) {
    float2 A[4], B[4];
    load_quad(fb, k1,  j1,  A);
    load_quad(fb, k1B, j1B, B);
    dft4(A[0], A[1], A[2], A[3]);   // A[j2] = X[k1+16*j1+256*j2]
    dft4(B[0], B[1], B[2], B[3]);
    const int kb = k1 + 16 * j1;
    #pragma unroll
    for (int j2 = 0; j2 < 4; j2++) {
        int kd = kb + 256 * j2;
        int k  = (j2 < 2) ? kd : (1024 - kd);   // pick the member < 513
        pair_mags(mag, k, v2, A[j2], B[3 - j2]);
    }
}

extern __shared__ __align__(16) float smem_dyn[];

__global__ void __launch_bounds__(THREADS)
stft_mag_kernel(const float* __restrict__ in, float* __restrict__ out) {
    float2* buf = (float2*)smem_dyn;              // 4 FFTs x 1024 complex = 32 KB
    float*  mag = (float*)(buf + 4 * N_FFT);      // 513*MP floats = 20.5 KB
    float2* Wt  = (float2*)(mag + CUTOFF * MP);   // 64 twiddles W1024^j (512 B)

    const int tid  = threadIdx.x;
    const int v    = tid >> 6;       // FFT slot 0..3
    const int w    = tid & 63;       // lane within FFT
    const int v2   = 2 * v;
    const int bidx = blockIdx.y;
    const int n0   = blockIdx.x * TILE;
    float2* fb = buf + v * N_FFT;

    const int  f0   = n0 + 2 * v;
    const bool f1ok = (f0 + 1) < N_FRAMES;
    const float* gr = in + (size_t)bidx * T_LEN + (size_t)f0 * HOP;

    // Twiddle base table: Wt[j] = W1024^j = exp(-2*pi*i*j/1024), j in [0,64).
    if (tid < 64) {
        float sn, cs;
        sincospif(-(float)tid * (1.0f / 512.0f), &sn, &cs);
        Wt[tid] = make_float2(cs, sn);
    }
    __syncthreads();

    float2 z[16];

    // ---- S1: 16-pt DFT over n1 (global gather, coalesced), n2 = w ----
    {
        const int n2 = w;
        #pragma unroll
        for (int n1 = 0; n1 < 16; n1++) {
            float re = gr[64 * n1 + n2];
            float im = f1ok ? gr[HOP + 64 * n1 + n2] : 0.0f;
            z[n1] = make_float2(re, im);
        }
        dft16(z);
        float2 lo[4], hi[4];
        make_pows(Wt[n2], lo, hi);                           // W1024^{n2}
        #pragma unroll
        for (int k1 = 0; k1 < 16; k1++) {
            int slot = 4 * (k1 & 3) + (k1 >> 2);
            float2 val = cmul(cmul(z[slot], lo[k1 & 3]), hi[k1 >> 2]);
            fb[64 * k1 + (n2 ^ ((k1 & 3) << 2))] = val;      // n2 bits[2:3] swizzle
        }
    }
    __syncthreads();

    // ---- S2: 16-pt DFT over m1; thread = (k1 = w>>2, m2 = w&3); in-place ----
    {
        const int k1 = w >> 2, m2 = w & 3, kx = k1 & 3;
        #pragma unroll
        for (int m1 = 0; m1 < 16; m1++)
            z[m1] = fb[64 * k1 + 4 * (m1 ^ kx) + m2];
        dft16(z);
        float2 lo[4], hi[4];
        make_pows(Wt[16 * m2], lo, hi);                      // W64^{m2} = W1024^{16 m2}
        #pragma unroll
        for (int j1 = 0; j1 < 16; j1++) {
            int slot = 4 * (j1 & 3) + (j1 >> 2);
            float2 val = cmul(cmul(z[slot], lo[j1 & 3]), hi[j1 >> 2]);
            fb[64 * k1 + 4 * (j1 ^ kx) + m2] = val;          // in-place per thread
        }
    }
    __syncthreads();

    // ---- fused last radix-4 + conjugate unpack + magnitudes ----
    // Slot map s = w + 64i: k1 = 1+(s&7) varies per lane (mag banks <=2-way).
    // k1=8 slots with j1>=8 are duplicates; recycled as k1=0 orbits + specials.
    #pragma unroll
    for (int i = 0; i < 2; i++) {
        const int s = w + 64 * i;
        const int k1s = 1 + (s & 7);
        const int j1s = s >> 3;
        if (k1s == 8 && j1s >= 8) {
            const int r = j1s - 8;
            if (r < 7) {
                orbit_mags(fb, mag, v2, 0, 1 + r, 0, 15 - r);
            } else {
                // self-paired quads (0,0) and (0,8)
                float2 A[4];
                load_quad(fb, 0, 0, A);
                dft4(A[0], A[1], A[2], A[3]);   // X[0],X[256],X[512],X[768]
                *(float2*)(mag + 0 * MP + v2)   = make_float2(fabsf(A[0].x), fabsf(A[0].y));
                pair_mags(mag, 256, v2, A[1], A[3]);
                *(float2*)(mag + 512 * MP + v2) = make_float2(fabsf(A[2].x), fabsf(A[2].y));
                load_quad(fb, 0, 8, A);
                dft4(A[0], A[1], A[2], A[3]);   // X[128],X[384],X[640],X[896]
                pair_mags(mag, 128, v2, A[0], A[3]);
                pair_mags(mag, 384, v2, A[1], A[2]);
            }
        } else {
            orbit_mags(fb, mag, v2, k1s, j1s, (16 - k1s) & 15, 15 - j1s);
        }
    }
    __syncthreads();

    // ---- coalesced writeout: 8 contiguous frames per spectral row ----
    if (n0 + TILE <= N_FRAMES) {
        // Fast path (all blocks but the last): no bounds checks, unrolled strided walk.
        const int c0 = tid >> 3, t = tid & 7;
        float*       op = out + (size_t)bidx * CUTOFF * N_FRAMES + (size_t)c0 * N_FRAMES + n0 + t;
        const float* mp = mag + c0 * MP + t;
        #pragma unroll
        for (int r = 0; r < 16; r++)            // c = c0 + 32r covers 0..511
            op[(size_t)(32 * r) * N_FRAMES] = mp[32 * r * MP];
        if (tid < 8)
            out[(size_t)bidx * CUTOFF * N_FRAMES + (size_t)512 * N_FRAMES + n0 + tid]
                = mag[512 * MP + tid];
    } else {
        const int tile_n = N_FRAMES - n0;
        for (int idx = tid; idx < CUTOFF * TILE; idx += THREADS) {
            int c = idx >> 3, t = idx & 7;
            if (t < tile_n)
                out[((size_t)bidx * CUTOFF + c) * N_FRAMES + n0 + t] = mag[c * MP + t];
        }
    }
}

extern "C" void kernel_launch(void* const* d_in, const int* in_sizes, int n_in,
                              void* d_out, int out_size) {
    const float* in  = (const float*)d_in[0];
    float*       out = (float*)d_out;

    const int smem_bytes = 4 * N_FFT * sizeof(float2) + CUTOFF * MP * sizeof(float)
                         + 64 * sizeof(float2);
    cudaFuncSetAttribute(stft_mag_kernel,
                         cudaFuncAttributeMaxDynamicSharedMemorySize, smem_bytes);

    dim3 grid((N_FRAMES + TILE - 1) / TILE, BATCH);
    stft_mag_kernel<<<grid, THREADS, smem_bytes>>>(in, out);
}

// round 11
// speedup vs baseline: 1.0192x; 1.0192x over previous
#include <cuda_runtime.h>

#define N_FFT    1024
#define HOP      512
#define CUTOFF   513
#define BATCH    16
#define T_LEN    2097152
#define N_FRAMES 4095
#define TILE     8       // 8 frames = 4 pair-packed complex FFTs per block
#define THREADS  256
#define MP       9       // mag row pad (odd stride)

__device__ __forceinline__ float2 cmul(float2 a, float2 b) {
    return make_float2(a.x * b.x - a.y * b.y, a.x * b.y + a.y * b.x);
}

// In-register radix-4 butterfly (DIT, W4 = -i), outputs in natural order.
__device__ __forceinline__ void dft4(float2& a, float2& b, float2& c, float2& d) {
    float2 apc  = make_float2(a.x + c.x, a.y + c.y);
    float2 amc  = make_float2(a.x - c.x, a.y - c.y);
    float2 bpd  = make_float2(b.x + d.x, b.y + d.y);
    float2 jbmd = make_float2(-(b.y - d.y), b.x - d.x);   // i*(b-d)
    a = make_float2(apc.x + bpd.x, apc.y + bpd.y);
    b = make_float2(amc.x - jbmd.x, amc.y - jbmd.y);
    c = make_float2(apc.x - bpd.x, apc.y - bpd.y);
    d = make_float2(amc.x + jbmd.x, amc.y + jbmd.y);
}

// 16-point DFT fully in registers. Input z[n]; output y[k] at slot 4*(k&3)+(k>>2).
__device__ __forceinline__ void dft16(float2 z[16]) {
    #pragma unroll
    for (int b = 0; b < 4; b++) dft4(z[b], z[4 + b], z[8 + b], z[12 + b]);
    const float C1 = 0.9238795325112867f, S1 = 0.3826834323650898f, R2 = 0.7071067811865476f;
    const float2 W1 = make_float2( C1, -S1);
    const float2 W2 = make_float2( R2, -R2);
    const float2 W3 = make_float2( S1, -C1);
    const float2 W6 = make_float2(-R2, -R2);
    const float2 W9 = make_float2(-C1,  S1);
    z[5]  = cmul(z[5],  W1);
    z[9]  = cmul(z[9],  W2);
    z[13] = cmul(z[13], W3);
    z[6]  = cmul(z[6],  W2);
    z[10] = make_float2(z[10].y, -z[10].x);   // * W16^4 = -i
    z[14] = cmul(z[14], W6);
    z[7]  = cmul(z[7],  W3);
    z[11] = cmul(z[11], W6);
    z[15] = cmul(z[15], W9);
    #pragma unroll
    for (int c = 0; c < 4; c++) dft4(z[4*c], z[4*c + 1], z[4*c + 2], z[4*c + 3]);
}

// lo[i] = t^i, hi[i] = t^(4i): acc(k) = lo[k&3]*hi[k>>2], short dep chains.
__device__ __forceinline__ void make_pows(float2 t, float2 lo[4], float2 hi[4]) {
    lo[0] = make_float2(1.f, 0.f);
    lo[1] = t;
    lo[2] = cmul(t, t);
    lo[3] = cmul(lo[2], t);
    hi[0] = make_float2(1.f, 0.f);
    hi[1] = cmul(lo[2], lo[2]);
    hi[2] = cmul(hi[1], hi[1]);
    hi[3] = cmul(hi[2], hi[1]);
}

// Read quad (K,J): 4 contiguous complex m2-values -> 2x LDS.128 (<=2-way).
__device__ __forceinline__ void load_quad(const float2* __restrict__ fb, int K, int J, float2 q[4]) {
    const float4* p = (const float4*)(fb + 64 * K + 4 * (J ^ (K & 3)));
    float4 h0 = p[0], h1 = p[1];
    q[0] = make_float2(h0.x, h0.y);
    q[1] = make_float2(h0.z, h0.w);
    q[2] = make_float2(h1.x, h1.y);
    q[3] = make_float2(h1.z, h1.w);
}

// P,Q conjugate pair of the pair-packed FFT -> two frame magnitudes at bin k.
// |0.5*z| = 0.5*|z| folded into one constant; sqrt(s) = s*rsqrt(s), MUFU.RSQ
// plus 2 FMUL instead of the precise-sqrtf refinement sequence. +1e-30 guards s==0.
__device__ __forceinline__ void pair_mags(float* mag, int k, int v2, float2 P, float2 Q) {
    float Ar = P.x + Q.x, Ai = P.y - Q.y;
    float Br = P.y + Q.y, Bi = Q.x - P.x;
    float sa = fmaf(Ar, Ar, Ai * Ai) + 1e-30f;
    float sb = fmaf(Br, Br, Bi * Bi) + 1e-30f;
    mag[k * MP + v2    ] = 0.5f * (sa * __frsqrt_rn(sa));
    mag[k * MP + v2 + 1] = 0.5f * (sb * __frsqrt_rn(sb));
}

// One orbit: quad A=(k1,j1) and its conjugate quad B. Emits 4 bins.
__device__ __forceinline__ void orbit_mags(const float2* __restrict__ fb, float* mag, int v2,
                                           int k1, int j1, int k1B, int j1B) {
    float2 A[4], B[4];
    load_quad(fb, k1,  j1,  A);
    load_quad(fb, k1B, j1B, B);
    dft4(A[0], A[1], A[2], A[3]);   // A[j2] = X[k1+16*j1+256*j2]
    dft4(B[0], B[1], B[2], B[3]);
    const int kb = k1 + 16 * j1;
    #pragma unroll
    for (int j2 = 0; j2 < 4; j2++) {
        int kd = kb + 256 * j2;
        int k  = (j2 < 2) ? kd : (1024 - kd);   // pick the member < 513
        pair_mags(mag, k, v2, A[j2], B[3 - j2]);
    }
}

extern __shared__ __align__(16) float smem_dyn[];

__global__ void __launch_bounds__(THREADS)
stft_mag_kernel(const float* __restrict__ in, float* __restrict__ out) {
    float2* buf = (float2*)smem_dyn;              // 4 FFTs x 1024 complex = 32 KB
    float*  mag = (float*)(buf + 4 * N_FFT);      // 513*MP floats = 18.5 KB

    const int tid  = threadIdx.x;
    const int v    = tid >> 6;       // FFT slot 0..3
    const int w    = tid & 63;       // lane within FFT
    const int v2   = 2 * v;
    const int bidx = blockIdx.y;
    const int n0   = blockIdx.x * TILE;
    float2* fb = buf + v * N_FFT;

    const int  f0   = n0 + 2 * v;
    const bool f1ok = (f0 + 1) < N_FRAMES;
    const float* gr = in + (size_t)bidx * T_LEN + (size_t)f0 * HOP;

    float2 z[16];

    // ---- S1: 16-pt DFT over n1 (global gather, coalesced), n2 = w ----
    {
        const int n2 = w;
        #pragma unroll
        for (int n1 = 0; n1 < 16; n1++) {
            float re = gr[64 * n1 + n2];
            float im = f1ok ? gr[HOP + 64 * n1 + n2] : 0.0f;
            z[n1] = make_float2(re, im);
        }
        dft16(z);
        float sn, cs;
        sincospif(-(float)n2 * (1.0f / 512.0f), &sn, &cs);   // W1024^{n2}
        float2 lo[4], hi[4];
        make_pows(make_float2(cs, sn), lo, hi);
        #pragma unroll
        for (int k1 = 0; k1 < 16; k1++) {
            int slot = 4 * (k1 & 3) + (k1 >> 2);
            float2 val = cmul(cmul(z[slot], lo[k1 & 3]), hi[k1 >> 2]);
            fb[64 * k1 + (n2 ^ ((k1 & 3) << 2))] = val;      // n2 bits[2:3] swizzle
        }
    }
    __syncthreads();

    // ---- S2: 16-pt DFT over m1; thread = (k1 = w>>2, m2 = w&3); in-place ----
    {
        const int k1 = w >> 2, m2 = w & 3, kx = k1 & 3;
        #pragma unroll
        for (int m1 = 0; m1 < 16; m1++)
            z[m1] = fb[64 * k1 + 4 * (m1 ^ kx) + m2];
        dft16(z);
        float sn, cs;
        sincospif(-(float)m2 * (1.0f / 32.0f), &sn, &cs);    // W64^{m2}
        float2 lo[4], hi[4];
        make_pows(make_float2(cs, sn), lo, hi);
        #pragma unroll
        for (int j1 = 0; j1 < 16; j1++) {
            int slot = 4 * (j1 & 3) + (j1 >> 2);
            float2 val = cmul(cmul(z[slot], lo[j1 & 3]), hi[j1 >> 2]);
            fb[64 * k1 + 4 * (j1 ^ kx) + m2] = val;          // in-place per thread
        }
    }
    __syncthreads();

    // ---- fused last radix-4 + conjugate unpack + magnitudes ----
    // Slot map s = w + 64i: k1 = 1+(s&7) varies per lane -> mag-store banks
    // k mod 32 = k1 + 16*(j1&1) are distinct per phase (<=2-way overall).
    // k1=8 slots with j1>=8 are duplicates; recycled as k1=0 orbits + specials.
    #pragma unroll
    for (int i = 0; i < 2; i++) {
        const int s = w + 64 * i;
        const int k1s = 1 + (s & 7);
        const int j1s = s >> 3;
        if (k1s == 8 && j1s >= 8) {
            const int r = j1s - 8;
            if (r < 7) {
                // k1=0 orbit: (0, 1+r) paired with (0, 15-r)
                orbit_mags(fb, mag, v2, 0, 1 + r, 0, 15 - r);
            } else {
                // self-paired quads (0,0) and (0,8)
                float2 A[4];
                load_quad(fb, 0, 0, A);
                dft4(A[0], A[1], A[2], A[3]);   // X[0],X[256],X[512],X[768]
                mag[0 * MP + v2]       = fabsf(A[0].x);
                mag[0 * MP + v2 + 1]   = fabsf(A[0].y);
                pair_mags(mag, 256, v2, A[1], A[3]);
                mag[512 * MP + v2]     = fabsf(A[2].x);
                mag[512 * MP + v2 + 1] = fabsf(A[2].y);
                load_quad(fb, 0, 8, A);
                dft4(A[0], A[1], A[2], A[3]);   // X[128],X[384],X[640],X[896]
                pair_mags(mag, 128, v2, A[0], A[3]);
                pair_mags(mag, 384, v2, A[1], A[2]);
            }
        } else {
            // generic orbit: (k1s, j1s) paired with (16-k1s, 15-j1s)
            orbit_mags(fb, mag, v2, k1s, j1s, (16 - k1s) & 15, 15 - j1s);
        }
    }
    __syncthreads();

    // ---- coalesced writeout: 8 contiguous frames per spectral row ----
    const int tile_n = min(TILE, N_FRAMES - n0);
    for (int idx = tid; idx < CUTOFF * TILE; idx += THREADS) {
        int c = idx >> 3, t = idx & 7;
        if (t < tile_n)
            out[((size_t)bidx * CUTOFF + c) * N_FRAMES + n0 + t] = mag[c * MP + t];
    }
}

extern "C" void kernel_launch(void* const* d_in, const int* in_sizes, int n_in,
                              void* d_out, int out_size) {
    const float* in  = (const float*)d_in[0];
    float*       out = (float*)d_out;

    const int smem_bytes = 4 * N_FFT * sizeof(float2) + CUTOFF * MP * sizeof(float);
    cudaFuncSetAttribute(stft_mag_kernel,
                         cudaFuncAttributeMaxDynamicSharedMemorySize, smem_bytes);

    dim3 grid((N_FRAMES + TILE - 1) / TILE, BATCH);
    stft_mag_kernel<<<grid, THREADS, smem_bytes>>>(in, out);
}

// round 12
// speedup vs baseline: 1.2413x; 1.2179x over previous
#include <cuda_runtime.h>

#define N_FFT    1024
#define HOP      512
#define CUTOFF   513
#define BATCH    16
#define T_LEN    2097152
#define N_FRAMES 4095
#define TILE     8       // 8 frames = 4 pair-packed complex FFTs per block
#define THREADS  256
#define MP       9       // mag row pad (odd stride)

__device__ __forceinline__ float2 cmul(float2 a, float2 b) {
    return make_float2(a.x * b.x - a.y * b.y, a.x * b.y + a.y * b.x);
}

// Single-instruction approximate sqrt: PTX sqrt.approx.f32 -> MUFU.SQRT.
// Max rel err ~2^-22, far below the 1e-3 test threshold. sqrt.approx(0) = 0.
__device__ __forceinline__ float fsqrt_approx(float x) {
    float r;
    asm("sqrt.approx.f32 %0, %1;" : "=f"(r) : "f"(x));
    return r;
}

// In-register radix-4 butterfly (DIT, W4 = -i), outputs in natural order.
__device__ __forceinline__ void dft4(float2& a, float2& b, float2& c, float2& d) {
    float2 apc  = make_float2(a.x + c.x, a.y + c.y);
    float2 amc  = make_float2(a.x - c.x, a.y - c.y);
    float2 bpd  = make_float2(b.x + d.x, b.y + d.y);
    float2 jbmd = make_float2(-(b.y - d.y), b.x - d.x);   // i*(b-d)
    a = make_float2(apc.x + bpd.x, apc.y + bpd.y);
    b = make_float2(amc.x - jbmd.x, amc.y - jbmd.y);
    c = make_float2(apc.x - bpd.x, apc.y - bpd.y);
    d = make_float2(amc.x + jbmd.x, amc.y + jbmd.y);
}

// 16-point DFT fully in registers. Input z[n]; output y[k] at slot 4*(k&3)+(k>>2).
__device__ __forceinline__ void dft16(float2 z[16]) {
    #pragma unroll
    for (int b = 0; b < 4; b++) dft4(z[b], z[4 + b], z[8 + b], z[12 + b]);
    const float C1 = 0.9238795325112867f, S1 = 0.3826834323650898f, R2 = 0.7071067811865476f;
    const float2 W1 = make_float2( C1, -S1);
    const float2 W2 = make_float2( R2, -R2);
    const float2 W3 = make_float2( S1, -C1);
    const float2 W6 = make_float2(-R2, -R2);
    const float2 W9 = make_float2(-C1,  S1);
    z[5]  = cmul(z[5],  W1);
    z[9]  = cmul(z[9],  W2);
    z[13] = cmul(z[13], W3);
    z[6]  = cmul(z[6],  W2);
    z[10] = make_float2(z[10].y, -z[10].x);   // * W16^4 = -i
    z[14] = cmul(z[14], W6);
    z[7]  = cmul(z[7],  W3);
    z[11] = cmul(z[11], W6);
    z[15] = cmul(z[15], W9);
    #pragma unroll
    for (int c = 0; c < 4; c++) dft4(z[4*c], z[4*c + 1], z[4*c + 2], z[4*c + 3]);
}

// lo[i] = t^i, hi[i] = t^(4i): acc(k) = lo[k&3]*hi[k>>2], short dep chains.
__device__ __forceinline__ void make_pows(float2 t, float2 lo[4], float2 hi[4]) {
    lo[0] = make_float2(1.f, 0.f);
    lo[1] = t;
    lo[2] = cmul(t, t);
    lo[3] = cmul(lo[2], t);
    hi[0] = make_float2(1.f, 0.f);
    hi[1] = cmul(lo[2], lo[2]);
    hi[2] = cmul(hi[1], hi[1]);
    hi[3] = cmul(hi[2], hi[1]);
}

// Read quad (K,J): 4 contiguous complex m2-values -> 2x LDS.128 (<=2-way).
__device__ __forceinline__ void load_quad(const float2* __restrict__ fb, int K, int J, float2 q[4]) {
    const float4* p = (const float4*)(fb + 64 * K + 4 * (J ^ (K & 3)));
    float4 h0 = p[0], h1 = p[1];
    q[0] = make_float2(h0.x, h0.y);
    q[1] = make_float2(h0.z, h0.w);
    q[2] = make_float2(h1.x, h1.y);
    q[3] = make_float2(h1.z, h1.w);
}

// P,Q conjugate pair of the pair-packed FFT -> two frame magnitudes at bin k.
// |0.5*z| = 0.5*|z| folded into one constant; sqrt via single MUFU.SQRT.
__device__ __forceinline__ void pair_mags(float* mag, int k, int v2, float2 P, float2 Q) {
    float Ar = P.x + Q.x, Ai = P.y - Q.y;
    float Br = P.y + Q.y, Bi = Q.x - P.x;
    float sa = fmaf(Ar, Ar, Ai * Ai);
    float sb = fmaf(Br, Br, Bi * Bi);
    mag[k * MP + v2    ] = 0.5f * fsqrt_approx(sa);
    mag[k * MP + v2 + 1] = 0.5f * fsqrt_approx(sb);
}

// One orbit: quad A=(k1,j1) and its conjugate quad B. Emits 4 bins.
__device__ __forceinline__ void orbit_mags(const float2* __restrict__ fb, float* mag, int v2,
                                           int k1, int j1, int k1B, int j1B) {
    float2 A[4], B[4];
    load_quad(fb, k1,  j1,  A);
    load_quad(fb, k1B, j1B, B);
    dft4(A[0], A[1], A[2], A[3]);   // A[j2] = X[k1+16*j1+256*j2]
    dft4(B[0], B[1], B[2], B[3]);
    const int kb = k1 + 16 * j1;
    #pragma unroll
    for (int j2 = 0; j2 < 4; j2++) {
        int kd = kb + 256 * j2;
        int k  = (j2 < 2) ? kd : (1024 - kd);   // pick the member < 513
        pair_mags(mag, k, v2, A[j2], B[3 - j2]);
    }
}

extern __shared__ __align__(16) float smem_dyn[];

__global__ void __launch_bounds__(THREADS)
stft_mag_kernel(const float* __restrict__ in, float* __restrict__ out) {
    float2* buf = (float2*)smem_dyn;              // 4 FFTs x 1024 complex = 32 KB
    float*  mag = (float*)(buf + 4 * N_FFT);      // 513*MP floats = 18.5 KB

    const int tid  = threadIdx.x;
    const int v    = tid >> 6;       // FFT slot 0..3
    const int w    = tid & 63;       // lane within FFT
    const int v2   = 2 * v;
    const int bidx = blockIdx.y;
    const int n0   = blockIdx.x * TILE;
    float2* fb = buf + v * N_FFT;

    const int  f0   = n0 + 2 * v;
    const bool f1ok = (f0 + 1) < N_FRAMES;
    const float* gr = in + (size_t)bidx * T_LEN + (size_t)f0 * HOP;

    float2 z[16];

    // ---- S1: 16-pt DFT over n1 (global gather, coalesced), n2 = w ----
    {
        const int n2 = w;
        #pragma unroll
        for (int n1 = 0; n1 < 16; n1++) {
            float re = gr[64 * n1 + n2];
            float im = f1ok ? gr[HOP + 64 * n1 + n2] : 0.0f;
            z[n1] = make_float2(re, im);
        }
        dft16(z);
        float sn, cs;
        sincospif(-(float)n2 * (1.0f / 512.0f), &sn, &cs);   // W1024^{n2}
        float2 lo[4], hi[4];
        make_pows(make_float2(cs, sn), lo, hi);
        #pragma unroll
        for (int k1 = 0; k1 < 16; k1++) {
            int slot = 4 * (k1 & 3) + (k1 >> 2);
            float2 val = cmul(cmul(z[slot], lo[k1 & 3]), hi[k1 >> 2]);
            fb[64 * k1 + (n2 ^ ((k1 & 3) << 2))] = val;      // n2 bits[2:3] swizzle
        }
    }
    __syncthreads();

    // ---- S2: 16-pt DFT over m1; thread = (k1 = w>>2, m2 = w&3); in-place ----
    {
        const int k1 = w >> 2, m2 = w & 3, kx = k1 & 3;
        #pragma unroll
        for (int m1 = 0; m1 < 16; m1++)
            z[m1] = fb[64 * k1 + 4 * (m1 ^ kx) + m2];
        dft16(z);
        float sn, cs;
        sincospif(-(float)m2 * (1.0f / 32.0f), &sn, &cs);    // W64^{m2}
        float2 lo[4], hi[4];
        make_pows(make_float2(cs, sn), lo, hi);
        #pragma unroll
        for (int j1 = 0; j1 < 16; j1++) {
            int slot = 4 * (j1 & 3) + (j1 >> 2);
            float2 val = cmul(cmul(z[slot], lo[j1 & 3]), hi[j1 >> 2]);
            fb[64 * k1 + 4 * (j1 ^ kx) + m2] = val;          // in-place per thread
        }
    }
    __syncthreads();

    // ---- fused last radix-4 + conjugate unpack + magnitudes ----
    // Slot map s = w + 64i: k1 = 1+(s&7) varies per lane -> mag-store banks
    // k mod 32 = k1 + 16*(j1&1) are distinct per phase (<=2-way overall).
    // k1=8 slots with j1>=8 are duplicates; recycled as k1=0 orbits + specials.
    #pragma unroll
    for (int i = 0; i < 2; i++) {
        const int s = w + 64 * i;
        const int k1s = 1 + (s & 7);
        const int j1s = s >> 3;
        if (k1s == 8 && j1s >= 8) {
            const int r = j1s - 8;
            if (r < 7) {
                // k1=0 orbit: (0, 1+r) paired with (0, 15-r)
                orbit_mags(fb, mag, v2, 0, 1 + r, 0, 15 - r);
            } else {
                // self-paired quads (0,0) and (0,8)
                float2 A[4];
                load_quad(fb, 0, 0, A);
                dft4(A[0], A[1], A[2], A[3]);   // X[0],X[256],X[512],X[768]
                mag[0 * MP + v2]       = fabsf(A[0].x);
                mag[0 * MP + v2 + 1]   = fabsf(A[0].y);
                pair_mags(mag, 256, v2, A[1], A[3]);
                mag[512 * MP + v2]     = fabsf(A[2].x);
                mag[512 * MP + v2 + 1] = fabsf(A[2].y);
                load_quad(fb, 0, 8, A);
                dft4(A[0], A[1], A[2], A[3]);   // X[128],X[384],X[640],X[896]
                pair_mags(mag, 128, v2, A[0], A[3]);
                pair_mags(mag, 384, v2, A[1], A[2]);
            }
        } else {
            // generic orbit: (k1s, j1s) paired with (16-k1s, 15-j1s)
            orbit_mags(fb, mag, v2, k1s, j1s, (16 - k1s) & 15, 15 - j1s);
        }
    }
    __syncthreads();

    // ---- coalesced writeout: 8 contiguous frames per spectral row ----
    const int tile_n = min(TILE, N_FRAMES - n0);
    for (int idx = tid; idx < CUTOFF * TILE; idx += THREADS) {
        int c = idx >> 3, t = idx & 7;
        if (t < tile_n)
            out[((size_t)bidx * CUTOFF + c) * N_FRAMES + n0 + t] = mag[c * MP + t];
    }
}

extern "C" void kernel_launch(void* const* d_in, const int* in_sizes, int n_in,
                              void* d_out, int out_size) {
    const float* in  = (const float*)d_in[0];
    float*       out = (float*)d_out;

    const int smem_bytes = 4 * N_FFT * sizeof(float2) + CUTOFF * MP * sizeof(float);
    cudaFuncSetAttribute(stft_mag_kernel,
                         cudaFuncAttributeMaxDynamicSharedMemorySize, smem_bytes);

    dim3 grid((N_FRAMES + TILE - 1) / TILE, BATCH);
    stft_mag_kernel<<<grid, THREADS, smem_bytes>>>(in, out);
}

// round 14
// speedup vs baseline: 1.3419x; 1.0810x over previous
#include <cuda_runtime.h>

#define N_FFT    1024
#define HOP      512
#define CUTOFF   513
#define BATCH    16
#define T_LEN    2097152
#define N_FRAMES 4095
#define TILE     8       // 8 frames = 4 pair-packed complex FFTs per block
#define THREADS  256
#define MP       9       // mag row pad (odd stride)

__device__ __forceinline__ float2 cmul(float2 a, float2 b) {
    return make_float2(a.x * b.x - a.y * b.y, a.x * b.y + a.y * b.x);
}

// Single-instruction approximate sqrt: PTX sqrt.approx.f32 -> MUFU.SQRT.
// Max rel err ~2^-22, far below the 1e-3 test threshold. sqrt.approx(0) = 0.
__device__ __forceinline__ float fsqrt_approx(float x) {
    float r;
    asm("sqrt.approx.f32 %0, %1;" : "=f"(r) : "f"(x));
    return r;
}

// In-register radix-4 butterfly (DIT, W4 = -i), outputs in natural order.
// Packed f32x2 formulation: 8 ADD2/FMA2 ops instead of 16 scalar FADDs.
// (ptxas does not auto-fuse scalar pairs; f32x2 is PTX-only on sm_103a.)
__device__ __forceinline__ void dft4(float2& a, float2& b, float2& c, float2& d) {
    asm("{\n\t"
        ".reg .b64 ra, rb, rc, rd, apc, amc, bpd, bmd, sw, rn1, rpm, rmp;\n\t"
        ".reg .f32 t0, t1;\n\t"
        "mov.b64 rn1, 0xBF800000BF800000;\n\t"   // {-1, -1}
        "mov.b64 rpm, 0xBF8000003F800000;\n\t"   // {+1, -1}  (lo=+1, hi=-1)
        "mov.b64 rmp, 0x3F800000BF800000;\n\t"   // {-1, +1}
        "mov.b64 ra, {%0, %1};\n\t"
        "mov.b64 rb, {%2, %3};\n\t"
        "mov.b64 rc, {%4, %5};\n\t"
        "mov.b64 rd, {%6, %7};\n\t"
        "add.rn.f32x2 apc, ra, rc;\n\t"
        "fma.rn.f32x2 amc, rc, rn1, ra;\n\t"     // a - c
        "add.rn.f32x2 bpd, rb, rd;\n\t"
        "fma.rn.f32x2 bmd, rd, rn1, rb;\n\t"     // b - d
        "mov.b64 {t0, t1}, bmd;\n\t"
        "mov.b64 sw, {t1, t0};\n\t"              // {bmd.y, bmd.x}
        "add.rn.f32x2 ra, apc, bpd;\n\t"         // out a = apc + bpd
        "fma.rn.f32x2 rc, bpd, rn1, apc;\n\t"    // out c = apc - bpd
        "fma.rn.f32x2 rb, sw, rpm, amc;\n\t"     // out b = (amc.x+bmd.y, amc.y-bmd.x)
        "fma.rn.f32x2 rd, sw, rmp, amc;\n\t"     // out d = (amc.x-bmd.y, amc.y+bmd.x)
        "mov.b64 {%0, %1}, ra;\n\t"
        "mov.b64 {%2, %3}, rb;\n\t"
        "mov.b64 {%4, %5}, rc;\n\t"
        "mov.b64 {%6, %7}, rd;\n\t"
        "}"
        : "+f"(a.x), "+f"(a.y), "+f"(b.x), "+f"(b.y),
          "+f"(c.x), "+f"(c.y), "+f"(d.x), "+f"(d.y));
}

// 16-point DFT fully in registers. Input z[n]; output y[k] at slot 4*(k&3)+(k>>2).
__device__ __forceinline__ void dft16(float2 z[16]) {
    #pragma unroll
    for (int b = 0; b < 4; b++) dft4(z[b], z[4 + b], z[8 + b], z[12 + b]);
    const float C1 = 0.9238795325112867f, S1 = 0.3826834323650898f, R2 = 0.7071067811865476f;
    const float2 W1 = make_float2( C1, -S1);
    const float2 W2 = make_float2( R2, -R2);
    const float2 W3 = make_float2( S1, -C1);
    const float2 W6 = make_float2(-R2, -R2);
    const float2 W9 = make_float2(-C1,  S1);
    z[5]  = cmul(z[5],  W1);
    z[9]  = cmul(z[9],  W2);
    z[13] = cmul(z[13], W3);
    z[6]  = cmul(z[6],  W2);
    z[10] = make_float2(z[10].y, -z[10].x);   // * W16^4 = -i
    z[14] = cmul(z[14], W6);
    z[7]  = cmul(z[7],  W3);
    z[11] = cmul(z[11], W6);
    z[15] = cmul(z[15], W9);
    #pragma unroll
    for (int c = 0; c < 4; c++) dft4(z[4*c], z[4*c + 1], z[4*c + 2], z[4*c + 3]);
}

// lo[i] = t^i, hi[i] = t^(4i): acc(k) = lo[k&3]*hi[k>>2], short dep chains.
__device__ __forceinline__ void make_pows(float2 t, float2 lo[4], float2 hi[4]) {
    lo[0] = make_float2(1.f, 0.f);
    lo[1] = t;
    lo[2] = cmul(t, t);
    lo[3] = cmul(lo[2], t);
    hi[0] = make_float2(1.f, 0.f);
    hi[1] = cmul(lo[2], lo[2]);
    hi[2] = cmul(hi[1], hi[1]);
    hi[3] = cmul(hi[2], hi[1]);
}

// Read quad (K,J): 4 contiguous complex m2-values -> 2x LDS.128 (<=2-way).
__device__ __forceinline__ void load_quad(const float2* __restrict__ fb, int K, int J, float2 q[4]) {
    const float4* p = (const float4*)(fb + 64 * K + 4 * (J ^ (K & 3)));
    float4 h0 = p[0], h1 = p[1];
    q[0] = make_float2(h0.x, h0.y);
    q[1] = make_float2(h0.z, h0.w);
    q[2] = make_float2(h1.x, h1.y);
    q[3] = make_float2(h1.z, h1.w);
}

// P,Q conjugate pair of the pair-packed FFT -> two frame magnitudes at bin k.
// |0.5*z| = 0.5*|z| folded into one constant; sqrt via single MUFU.SQRT.
__device__ __forceinline__ void pair_mags(float* mag, int k, int v2, float2 P, float2 Q) {
    float Ar = P.x + Q.x, Ai = P.y - Q.y;
    float Br = P.y + Q.y, Bi = Q.x - P.x;
    float sa = fmaf(Ar, Ar, Ai * Ai);
    float sb = fmaf(Br, Br, Bi * Bi);
    mag[k * MP + v2    ] = 0.5f * fsqrt_approx(sa);
    mag[k * MP + v2 + 1] = 0.5f * fsqrt_approx(sb);
}

// One orbit: quad A=(k1,j1) and its conjugate quad B. Emits 4 bins.
__device__ __forceinline__ void orbit_mags(const float2* __restrict__ fb, float* mag, int v2,
                                           int k1, int j1, int k1B, int j1B) {
    float2 A[4], B[4];
    load_quad(fb, k1,  j1,  A);
    load_quad(fb, k1B, j1B, B);
    dft4(A[0], A[1], A[2], A[3]);   // A[j2] = X[k1+16*j1+256*j2]
    dft4(B[0], B[1], B[2], B[3]);
    const int kb = k1 + 16 * j1;
    #pragma unroll
    for (int j2 = 0; j2 < 4; j2++) {
        int kd = kb + 256 * j2;
        int k  = (j2 < 2) ? kd : (1024 - kd);   // pick the member < 513
        pair_mags(mag, k, v2, A[j2], B[3 - j2]);
    }
}

extern __shared__ __align__(16) float smem_dyn[];

__global__ void __launch_bounds__(THREADS)
stft_mag_kernel(const float* __restrict__ in, float* __restrict__ out) {
    float2* buf = (float2*)smem_dyn;              // 4 FFTs x 1024 complex = 32 KB
    float*  mag = (float*)(buf + 4 * N_FFT);      // 513*MP floats = 18.5 KB

    const int tid  = threadIdx.x;
    const int v    = tid >> 6;       // FFT slot 0..3
    const int w    = tid & 63;       // lane within FFT
    const int v2   = 2 * v;
    const int bidx = blockIdx.y;
    const int n0   = blockIdx.x * TILE;
    float2* fb = buf + v * N_FFT;

    const int  f0   = n0 + 2 * v;
    const bool f1ok = (f0 + 1) < N_FRAMES;
    const float* gr = in + (size_t)bidx * T_LEN + (size_t)f0 * HOP;

    float2 z[16];

    // ---- S1: 16-pt DFT over n1 (global gather, coalesced), n2 = w ----
    {
        const int n2 = w;
        #pragma unroll
        for (int n1 = 0; n1 < 16; n1++) {
            float re = gr[64 * n1 + n2];
            float im = f1ok ? gr[HOP + 64 * n1 + n2] : 0.0f;
            z[n1] = make_float2(re, im);
        }
        dft16(z);
        float sn, cs;
        sincospif(-(float)n2 * (1.0f / 512.0f), &sn, &cs);   // W1024^{n2}
        float2 lo[4], hi[4];
        make_pows(make_float2(cs, sn), lo, hi);
        #pragma unroll
        for (int k1 = 0; k1 < 16; k1++) {
            int slot = 4 * (k1 & 3) + (k1 >> 2);
            float2 val = cmul(cmul(z[slot], lo[k1 & 3]), hi[k1 >> 2]);
            fb[64 * k1 + (n2 ^ ((k1 & 3) << 2))] = val;      // n2 bits[2:3] swizzle
        }
    }
    __syncthreads();

    // ---- S2: 16-pt DFT over m1; thread = (k1 = w>>2, m2 = w&3); in-place ----
    {
        const int k1 = w >> 2, m2 = w & 3, kx = k1 & 3;
        #pragma unroll
        for (int m1 = 0; m1 < 16; m1++)
            z[m1] = fb[64 * k1 + 4 * (m1 ^ kx) + m2];
        dft16(z);
        float sn, cs;
        sincospif(-(float)m2 * (1.0f / 32.0f), &sn, &cs);    // W64^{m2}
        float2 lo[4], hi[4];
        make_pows(make_float2(cs, sn), lo, hi);
        #pragma unroll
        for (int j1 = 0; j1 < 16; j1++) {
            int slot = 4 * (j1 & 3) + (j1 >> 2);
            float2 val = cmul(cmul(z[slot], lo[j1 & 3]), hi[j1 >> 2]);
            fb[64 * k1 + 4 * (j1 ^ kx) + m2] = val;          // in-place per thread
        }
    }
    __syncthreads();

    // ---- fused last radix-4 + conjugate unpack + magnitudes ----
    // Slot map s = w + 64i: k1 = 1+(s&7) varies per lane -> mag-store banks
    // k mod 32 = k1 + 16*(j1&1) are distinct per phase (<=2-way overall).
    // k1=8 slots with j1>=8 are duplicates; recycled as k1=0 orbits + specials.
    #pragma unroll
    for (int i = 0; i < 2; i++) {
        const int s = w + 64 * i;
        const int k1s = 1 + (s & 7);
        const int j1s = s >> 3;
        if (k1s == 8 && j1s >= 8) {
            const int r = j1s - 8;
            if (r < 7) {
                // k1=0 orbit: (0, 1+r) paired with (0, 15-r)
                orbit_mags(fb, mag, v2, 0, 1 + r, 0, 15 - r);
            } else {
                // self-paired quads (0,0) and (0,8)
                float2 A[4];
                load_quad(fb, 0, 0, A);
                dft4(A[0], A[1], A[2], A[3]);   // X[0],X[256],X[512],X[768]
                mag[0 * MP + v2]       = fabsf(A[0].x);
                mag[0 * MP + v2 + 1]   = fabsf(A[0].y);
                pair_mags(mag, 256, v2, A[1], A[3]);
                mag[512 * MP + v2]     = fabsf(A[2].x);
                mag[512 * MP + v2 + 1] = fabsf(A[2].y);
                load_quad(fb, 0, 8, A);
                dft4(A[0], A[1], A[2], A[3]);   // X[128],X[384],X[640],X[896]
                pair_mags(mag, 128, v2, A[0], A[3]);
                pair_mags(mag, 384, v2, A[1], A[2]);
            }
        } else {
            // generic orbit: (k1s, j1s) paired with (16-k1s, 15-j1s)
            orbit_mags(fb, mag, v2, k1s, j1s, (16 - k1s) & 15, 15 - j1s);
        }
    }
    __syncthreads();

    // ---- coalesced writeout: 8 contiguous frames per spectral row ----
    const int tile_n = min(TILE, N_FRAMES - n0);
    for (int idx = tid; idx < CUTOFF * TILE; idx += THREADS) {
        int c = idx >> 3, t = idx & 7;
        if (t < tile_n)
            out[((size_t)bidx * CUTOFF + c) * N_FRAMES + n0 + t] = mag[c * MP + t];
    }
}

extern "C" void kernel_launch(void* const* d_in, const int* in_sizes, int n_in,
                              void* d_out, int out_size) {
    const float* in  = (const float*)d_in[0];
    float*       out = (float*)d_out;

    const int smem_bytes = 4 * N_FFT * sizeof(float2) + CUTOFF * MP * sizeof(float);
    cudaFuncSetAttribute(stft_mag_kernel,
                         cudaFuncAttributeMaxDynamicSharedMemorySize, smem_bytes);

    dim3 grid((N_FRAMES + TILE - 1) / TILE, BATCH);
    stft_mag_kernel<<<grid, THREADS, smem_bytes>>>(in, out);
}